// round 3
// baseline (speedup 1.0000x reference)
#include <cuda_runtime.h>

#define LSZ 4096
#define NBATCH 64
#define NX 1024
#define R1V 48
#define R2V 16
#define FCV 512
#define NCLS 10

// ---------------- device scratch (no allocations allowed) ----------------
__device__ float g_da1[LSZ], g_db1[LSZ], g_da2[LSZ], g_db2[LSZ];
__device__ float g_Gt1[R1V * LSZ], g_Ht1[R1V * LSZ];
__device__ float g_Gt2[R2V * LSZ], g_Ht2[R2V * LSZ];
__device__ float g_xb1[NBATCH * NX];
__device__ float g_M1[NX * LSZ];    // St1 then (in-place scanned) M1 transposed: [k<1024][j<4096]
__device__ float g_M2[FCV * LSZ];   // S2 then (in-place scanned) M2: [j<512][k<4096]
__device__ float g_part1[4 * NBATCH * LSZ];
__device__ float g_part2[32 * NBATCH * FCV];
__device__ float g_xb2[NBATCH * LSZ];
__device__ float g_h2[NBATCH * FCV];
__device__ float g_seg1[8 * (NX + LSZ - 1)];
__device__ float g_seg2[4 * (FCV + LSZ - 1)];

// ---------------- cumulative products d[i] = prod_{t<i} subd[t] ----------------
__global__ void cumprod_kernel(const float* sA1, const float* sB1,
                               const float* sA2, const float* sB2) {
    __shared__ float cp[256];
    const float* src;
    float* dst;
    if (blockIdx.x == 0)      { src = sA1; dst = g_da1; }
    else if (blockIdx.x == 1) { src = sB1; dst = g_db1; }
    else if (blockIdx.x == 2) { src = sA2; dst = g_da2; }
    else                      { src = sB2; dst = g_db2; }
    int t = threadIdx.x;
    int base = t * 16;
    float vals[16];
    float cum = 1.f;
#pragma unroll
    for (int q = 0; q < 16; q++) {
        vals[q] = cum;
        int si = base + q;
        if (si < LSZ - 1) cum *= src[si];
    }
    cp[t] = cum;
    __syncthreads();
    float v = cum;
    for (int off = 1; off < 256; off <<= 1) {
        float y = (t >= off) ? cp[t - off] : 1.f;
        __syncthreads();
        v *= y;
        cp[t] = v;
        __syncthreads();
    }
    float pre = (t > 0) ? cp[t - 1] : 1.f;
#pragma unroll
    for (int q = 0; q < 16; q++) dst[base + q] = pre * vals[q];
}

// ---------------- rescale G/H by 1/d, x by d_b ----------------
__global__ void scale_kernel(const float* __restrict__ x,
                             const float* __restrict__ G1, const float* __restrict__ H1,
                             const float* __restrict__ G2, const float* __restrict__ H2) {
    int i = blockIdx.x * 256 + threadIdx.x;
    if (i < R1V * LSZ) {
        int j = i & (LSZ - 1);
        g_Gt1[i] = G1[i] / g_da1[j];
        g_Ht1[i] = H1[i] / g_db1[j];
    }
    if (i < R2V * LSZ) {
        int j = i & (LSZ - 1);
        g_Gt2[i] = G2[i] / g_da2[j];
        g_Ht2[i] = H2[i] / g_db2[j];
    }
    if (i < NBATCH * NX) {
        int k = i & (NX - 1);
        g_xb1[i] = x[i] * g_db1[k];
    }
}

// ---------------- S = P^T Q over small rank r (outer-product GEMM) ----------------
// Out[r0+rr][c0+cc] = sum_i P[i][r0+rr] * Q[i][c0+cc]; Out has row length 4096.
__global__ __launch_bounds__(256) void sgemm_kernel(int which) {
    const float *P, *Q;
    float* Out;
    int r;
    if (which == 0) { P = g_Ht1; Q = g_Gt1; Out = g_M1; r = R1V; }  // St1[k][j]
    else            { P = g_Gt2; Q = g_Ht2; Out = g_M2; r = R2V; }  // S2[j][k]
    const int NC = LSZ;
    __shared__ float Ps[8][65];
    __shared__ float Qs[8][65];
    int c0 = blockIdx.x * 64;
    int r0 = blockIdx.y * 64;
    int tid = threadIdx.x;
    int tr = tid >> 4, tc = tid & 15;
    float acc[4][4] = {};
    for (int ib = 0; ib < r; ib += 8) {
#pragma unroll
        for (int ld = 0; ld < 2; ld++) {
            int idx = tid + ld * 256;
            int il = idx >> 6;
            int cc = idx & 63;
            Ps[il][cc] = P[(ib + il) * LSZ + r0 + cc];
            Qs[il][cc] = Q[(ib + il) * LSZ + c0 + cc];
        }
        __syncthreads();
#pragma unroll
        for (int il = 0; il < 8; il++) {
            float a[4], b[4];
#pragma unroll
            for (int p = 0; p < 4; p++) a[p] = Ps[il][tr * 4 + p];
#pragma unroll
            for (int q = 0; q < 4; q++) b[q] = Qs[il][tc * 4 + q];
#pragma unroll
            for (int p = 0; p < 4; p++)
#pragma unroll
                for (int q = 0; q < 4; q++) acc[p][q] += a[p] * b[q];
        }
        __syncthreads();
    }
#pragma unroll
    for (int p = 0; p < 4; p++)
#pragma unroll
        for (int q = 0; q < 4; q++)
            Out[(r0 + tr * 4 + p) * NC + c0 + tc * 4 + q] = acc[p][q];
}

// ---------------- segmented diagonal prefix scan (in-place S -> M) ----------------
__device__ __forceinline__ void diag_params(int g, int NR, int NC,
                                            int& r0, int& c0, int& len) {
    int o = g - (NR - 1);
    r0 = o < 0 ? -o : 0;
    c0 = o > 0 ? o : 0;
    int l1 = NR - r0, l2 = NC - c0;
    len = l1 < l2 ? l1 : l2;
}

__global__ void segsum_kernel(int which) {
    float* S;
    float* seg;
    int NR, nseg;
    if (which == 0) { S = g_M1; seg = g_seg1; NR = NX;  nseg = 8; }
    else            { S = g_M2; seg = g_seg2; NR = FCV; nseg = 4; }
    const int NC = LSZ, SL = 128;
    int NG = NR + NC - 1;
    int id = blockIdx.x * 256 + threadIdx.x;
    if (id >= NG * nseg) return;
    int s = id / NG, g = id - s * NG;
    int r0, c0, len;
    diag_params(g, NR, NC, r0, c0, len);
    int t0 = s * SL;
    int t1 = min(len, t0 + SL);
    float a = 0.f;
    int base = (r0 + t0) * NC + c0 + t0;
    for (int t = t0; t < t1; t++) { a += S[base]; base += NC + 1; }
    seg[id] = a;
}

__global__ void segscan_kernel(int which) {
    float* S;
    float* seg;
    int NR, nseg;
    if (which == 0) { S = g_M1; seg = g_seg1; NR = NX;  nseg = 8; }
    else            { S = g_M2; seg = g_seg2; NR = FCV; nseg = 4; }
    const int NC = LSZ, SL = 128;
    int NG = NR + NC - 1;
    int id = blockIdx.x * 256 + threadIdx.x;
    if (id >= NG * nseg) return;
    int s = id / NG, g = id - s * NG;
    int r0, c0, len;
    diag_params(g, NR, NC, r0, c0, len);
    int t0 = s * SL;
    int t1 = min(len, t0 + SL);
    float a = 0.f;
    for (int ss = 0; ss < s; ss++) a += seg[ss * NG + g];
    int base = (r0 + t0) * NC + c0 + t0;
    for (int t = t0; t < t1; t++) {
        a += S[base];
        S[base] = a;
        base += NC + 1;
    }
}

// ---------------- batched GEMM with K-split: part[split][b][j] = X @ W ----------------
// WHICH==0: X=xb1(64x1024), W=M1t stored [k][j] (row len 4096), kchunk=256, J=4096
// WHICH==1: X=xb2(64x4096), W=M2 stored [j][k] (row len 4096, transposed tile load),
//           kchunk=128, J=512
template <int WHICH>
__global__ __launch_bounds__(256) void gemm_kernel() {
    const float *X, *W;
    float* part;
    int K, J, kchunk;
    if (WHICH == 0) { X = g_xb1; W = g_M1; part = g_part1; K = NX;  J = LSZ; kchunk = 256; }
    else            { X = g_xb2; W = g_M2; part = g_part2; K = LSZ; J = FCV; kchunk = 128; }
    __shared__ float Xs[32][65];
    __shared__ float Ws[32][65];
    int j0 = blockIdx.x * 64;
    int k0 = blockIdx.y * kchunk;
    int tid = threadIdx.x;
    int tb = tid >> 4, tj = tid & 15;
    float acc[4][4] = {};
    for (int kk = k0; kk < k0 + kchunk; kk += 32) {
#pragma unroll
        for (int ld = 0; ld < 8; ld++) {
            int idx = tid + ld * 256;
            int b = idx >> 5;
            int kl = idx & 31;
            Xs[kl][b] = X[b * K + kk + kl];
        }
        if (WHICH == 0) {
#pragma unroll
            for (int ld = 0; ld < 8; ld++) {
                int idx = tid + ld * 256;
                int kl = idx >> 6;
                int jl = idx & 63;
                Ws[kl][jl] = W[(kk + kl) * LSZ + j0 + jl];
            }
        } else {
#pragma unroll
            for (int ld = 0; ld < 8; ld++) {
                int idx = tid + ld * 256;
                int jl = idx >> 5;
                int kl = idx & 31;
                Ws[kl][jl] = W[(j0 + jl) * LSZ + kk + kl];
            }
        }
        __syncthreads();
#pragma unroll
        for (int kl = 0; kl < 32; kl++) {
            float a[4], b[4];
#pragma unroll
            for (int p = 0; p < 4; p++) a[p] = Xs[kl][tb * 4 + p];
#pragma unroll
            for (int q = 0; q < 4; q++) b[q] = Ws[kl][tj * 4 + q];
#pragma unroll
            for (int p = 0; p < 4; p++)
#pragma unroll
                for (int q = 0; q < 4; q++) acc[p][q] += a[p] * b[q];
        }
        __syncthreads();
    }
    int split = blockIdx.y;
#pragma unroll
    for (int p = 0; p < 4; p++)
#pragma unroll
        for (int q = 0; q < 4; q++) {
            int b = tb * 4 + p;
            int j = j0 + tj * 4 + q;
            part[(split * NBATCH + b) * J + j] = acc[p][q];
        }
}

// ---------------- epilogues ----------------
__global__ void epi1_kernel(const float* __restrict__ bias1) {
    int i = blockIdx.x * 256 + threadIdx.x;
    if (i >= NBATCH * LSZ) return;
    int j = i & (LSZ - 1);
    float a = 0.f;
#pragma unroll
    for (int s = 0; s < 4; s++) a += g_part1[s * (NBATCH * LSZ) + i];
    float v = a * g_da1[j] + bias1[j];
    v = v > 0.f ? v : 0.f;
    g_xb2[i] = v * g_db2[j];
}

__global__ void epi2_kernel(const float* __restrict__ bias2) {
    int i = blockIdx.x * 256 + threadIdx.x;
    if (i >= NBATCH * FCV) return;
    int j = i & (FCV - 1);
    float a = 0.f;
#pragma unroll
    for (int s = 0; s < 32; s++) a += g_part2[s * (NBATCH * FCV) + i];
    float v = a * g_da2[j] + bias2[j];
    g_h2[i] = v > 0.f ? v : 0.f;
}

// ---------------- classifier: out[b][c] = h2[b] . W[c] + bias ----------------
__global__ void logits_kernel(const float* __restrict__ Wl,
                              const float* __restrict__ bl,
                              float* __restrict__ out) {
    int b = blockIdx.x;
    int w = threadIdx.x >> 5;
    int lane = threadIdx.x & 31;
    if (w >= NCLS) return;
    float a = 0.f;
    for (int j = lane; j < FCV; j += 32) a += g_h2[b * FCV + j] * Wl[w * FCV + j];
#pragma unroll
    for (int off = 16; off; off >>= 1) a += __shfl_xor_sync(0xffffffffu, a, off);
    if (lane == 0) out[b * NCLS + w] = a + bl[w];
}

extern "C" void kernel_launch(void* const* d_in, const int* in_sizes, int n_in,
                              void* d_out, int out_size) {
    const float* x    = (const float*)d_in[0];
    const float* G1   = (const float*)d_in[1];
    const float* H1   = (const float*)d_in[2];
    const float* sA1  = (const float*)d_in[3];
    const float* sB1  = (const float*)d_in[4];
    const float* b1   = (const float*)d_in[5];
    const float* G2   = (const float*)d_in[6];
    const float* H2   = (const float*)d_in[7];
    const float* sA2  = (const float*)d_in[8];
    const float* sB2  = (const float*)d_in[9];
    const float* b2   = (const float*)d_in[10];
    const float* Wl   = (const float*)d_in[11];
    const float* bl   = (const float*)d_in[12];
    float* out = (float*)d_out;

    cumprod_kernel<<<4, 256>>>(sA1, sB1, sA2, sB2);
    scale_kernel<<<(R1V * LSZ + 255) / 256, 256>>>(x, G1, H1, G2, H2);

    // Layer 1: St1 [1024][4096] -> diagonal scan -> M1t, then y1 = xb1 @ M1t
    sgemm_kernel<<<dim3(LSZ / 64, NX / 64), 256>>>(0);
    segsum_kernel<<<(8 * (NX + LSZ - 1) + 255) / 256, 256>>>(0);
    segscan_kernel<<<(8 * (NX + LSZ - 1) + 255) / 256, 256>>>(0);
    gemm_kernel<0><<<dim3(LSZ / 64, 4), 256>>>();
    epi1_kernel<<<(NBATCH * LSZ) / 256, 256>>>(b1);

    // Layer 2: S2 [512][4096] -> diagonal scan -> M2, then y2 = xb2 @ M2^T (512 rows)
    sgemm_kernel<<<dim3(LSZ / 64, FCV / 64), 256>>>(1);
    segsum_kernel<<<(4 * (FCV + LSZ - 1) + 255) / 256, 256>>>(1);
    segscan_kernel<<<(4 * (FCV + LSZ - 1) + 255) / 256, 256>>>(1);
    gemm_kernel<1><<<dim3(FCV / 64, 32), 256>>>();
    epi2_kernel<<<(NBATCH * FCV) / 256, 256>>>(b2);

    logits_kernel<<<NBATCH, 320>>>(Wl, bl, out);
}

// round 10
// speedup vs baseline: 1.7024x; 1.7024x over previous
#include <cuda_runtime.h>

#define LSZ 4096
#define NBATCH 64
#define NX 1024
#define R1V 48
#define R2V 16
#define FCV 512
#define NCLS 10

#define NG1 (NX + LSZ - 1)      // 5119 diagonals, layer 1
#define NG2 (FCV + LSZ - 1)     // 4607 diagonals, layer 2
#define SLEN 32                 // scan segment length
#define NSEG1 (NX / SLEN)       // 32
#define NSEG2 (FCV / SLEN)      // 16
#define C1 (NSEG1 * NG1)
#define C2 (NSEG2 * NG2)
#define KSPLIT1 8
#define KSPLIT2 32

// ---------------- device scratch (no allocations allowed) ----------------
__device__ float g_da1[LSZ], g_db1[LSZ], g_da2[LSZ], g_db2[LSZ];
__device__ float g_Gt1[R1V * LSZ], g_Ht1[R1V * LSZ];
__device__ float g_Gt2[R2V * LSZ], g_Ht2[R2V * LSZ];
__device__ float g_xb1[NBATCH * NX];
__device__ float g_M1[NX * LSZ];    // St1 then (in-place scanned) M1 transposed: [k<1024][j<4096]
__device__ float g_M2[FCV * LSZ];   // S2 then (in-place scanned) M2: [j<512][k<4096]
__device__ float g_part1[KSPLIT1 * NBATCH * LSZ];
__device__ float g_part2[KSPLIT2 * NBATCH * FCV];
__device__ float g_xb2[NBATCH * LSZ];
__device__ float g_h2[NBATCH * FCV];
__device__ float g_seg1[C1];
__device__ float g_seg2[C2];

// ---------------- cumulative products d[i] = prod_{t<i} subd[t] ----------------
__global__ void cumprod_kernel(const float* sA1, const float* sB1,
                               const float* sA2, const float* sB2) {
    __shared__ float cp[256];
    const float* src;
    float* dst;
    if (blockIdx.x == 0)      { src = sA1; dst = g_da1; }
    else if (blockIdx.x == 1) { src = sB1; dst = g_db1; }
    else if (blockIdx.x == 2) { src = sA2; dst = g_da2; }
    else                      { src = sB2; dst = g_db2; }
    int t = threadIdx.x;
    int base = t * 16;
    float vals[16];
    float cum = 1.f;
#pragma unroll
    for (int q = 0; q < 16; q++) {
        vals[q] = cum;
        int si = base + q;
        if (si < LSZ - 1) cum *= src[si];
    }
    cp[t] = cum;
    __syncthreads();
    float v = cum;
    for (int off = 1; off < 256; off <<= 1) {
        float y = (t >= off) ? cp[t - off] : 1.f;
        __syncthreads();
        v *= y;
        cp[t] = v;
        __syncthreads();
    }
    float pre = (t > 0) ? cp[t - 1] : 1.f;
#pragma unroll
    for (int q = 0; q < 16; q++) dst[base + q] = pre * vals[q];
}

// ---------------- rescale G/H by 1/d, x by d_b ----------------
__global__ void scale_kernel(const float* __restrict__ x,
                             const float* __restrict__ G1, const float* __restrict__ H1,
                             const float* __restrict__ G2, const float* __restrict__ H2) {
    int i = blockIdx.x * 256 + threadIdx.x;
    if (i < R1V * LSZ) {
        int j = i & (LSZ - 1);
        g_Gt1[i] = G1[i] / g_da1[j];
        g_Ht1[i] = H1[i] / g_db1[j];
    }
    if (i < R2V * LSZ) {
        int j = i & (LSZ - 1);
        g_Gt2[i] = G2[i] / g_da2[j];
        g_Ht2[i] = H2[i] / g_db2[j];
    }
    if (i < NBATCH * NX) {
        int k = i & (NX - 1);
        g_xb1[i] = x[i] * g_db1[k];
    }
}

// ---------------- S = P^T Q over small rank r, BOTH layers in one launch ----------------
// blockIdx.y < 16: layer 1 tile (St1[k][j] += Ht1[i,k]*Gt1[i,j], 1024x4096)
// else:            layer 2 tile (S2[j][k]  += Gt2[i,j]*Ht2[i,k],  512x4096)
__global__ __launch_bounds__(256) void sgemm_kernel() {
    const float *P, *Q;
    float* Out;
    int r, r0;
    if (blockIdx.y < NX / 64) {
        P = g_Ht1; Q = g_Gt1; Out = g_M1; r = R1V; r0 = blockIdx.y * 64;
    } else {
        P = g_Gt2; Q = g_Ht2; Out = g_M2; r = R2V; r0 = (blockIdx.y - NX / 64) * 64;
    }
    __shared__ float Ps[8][65];
    __shared__ float Qs[8][65];
    int c0 = blockIdx.x * 64;
    int tid = threadIdx.x;
    int tr = tid >> 4, tc = tid & 15;
    float acc[4][4] = {};
    for (int ib = 0; ib < r; ib += 8) {
#pragma unroll
        for (int ld = 0; ld < 2; ld++) {
            int idx = tid + ld * 256;
            int il = idx >> 6;
            int cc = idx & 63;
            Ps[il][cc] = P[(ib + il) * LSZ + r0 + cc];
            Qs[il][cc] = Q[(ib + il) * LSZ + c0 + cc];
        }
        __syncthreads();
#pragma unroll
        for (int il = 0; il < 8; il++) {
            float a[4], b[4];
#pragma unroll
            for (int p = 0; p < 4; p++) a[p] = Ps[il][tr * 4 + p];
#pragma unroll
            for (int q = 0; q < 4; q++) b[q] = Qs[il][tc * 4 + q];
#pragma unroll
            for (int p = 0; p < 4; p++)
#pragma unroll
                for (int q = 0; q < 4; q++) acc[p][q] += a[p] * b[q];
        }
        __syncthreads();
    }
#pragma unroll
    for (int p = 0; p < 4; p++)
#pragma unroll
        for (int q = 0; q < 4; q++)
            Out[(r0 + tr * 4 + p) * LSZ + c0 + tc * 4 + q] = acc[p][q];
}

// ---------------- segmented diagonal prefix scan (in-place S -> M), both layers ----------------
__device__ __forceinline__ void diag_params(int g, int NR, int NC,
                                            int& r0, int& c0, int& len) {
    int o = g - (NR - 1);
    r0 = o < 0 ? -o : 0;
    c0 = o > 0 ? o : 0;
    int l1 = NR - r0, l2 = NC - c0;
    len = l1 < l2 ? l1 : l2;
}

__device__ __forceinline__ bool seg_decode(int id, float*& S, float*& seg,
                                           int& NR, int& NG, int& s, int& g) {
    if (id < C1) {
        S = g_M1; seg = g_seg1; NR = NX; NG = NG1;
    } else {
        id -= C1;
        if (id >= C2) return false;
        S = g_M2; seg = g_seg2; NR = FCV; NG = NG2;
    }
    s = id / NG;
    g = id - s * NG;
    return true;
}

__global__ void segsum_kernel() {
    int id = blockIdx.x * 256 + threadIdx.x;
    float *S, *seg;
    int NR, NG, s, g;
    if (!seg_decode(id, S, seg, NR, NG, s, g)) return;
    int r0, c0, len;
    diag_params(g, NR, LSZ, r0, c0, len);
    int t0 = s * SLEN;
    int t1 = min(len, t0 + SLEN);
    float a = 0.f;
    int base = (r0 + t0) * LSZ + c0 + t0;
#pragma unroll 4
    for (int t = t0; t < t1; t++) { a += S[base]; base += LSZ + 1; }
    seg[s * NG + g] = a;
}

__global__ void segscan_kernel() {
    int id = blockIdx.x * 256 + threadIdx.x;
    float *S, *seg;
    int NR, NG, s, g;
    if (!seg_decode(id, S, seg, NR, NG, s, g)) return;
    int r0, c0, len;
    diag_params(g, NR, LSZ, r0, c0, len);
    int t0 = s * SLEN;
    int t1 = min(len, t0 + SLEN);
    float a = 0.f;
#pragma unroll 4
    for (int ss = 0; ss < s; ss++) a += seg[ss * NG + g];
    int base = (r0 + t0) * LSZ + c0 + t0;
#pragma unroll 4
    for (int t = t0; t < t1; t++) {
        a += S[base];
        S[base] = a;
        base += LSZ + 1;
    }
}

// ---------------- batched GEMM with K-split: part[split][b][j] = X @ W ----------------
// WHICH==0: X=xb1(64x1024), W=M1t stored [k][j] (row len 4096), kchunk=128, J=4096
// WHICH==1: X=xb2(64x4096), W=M2 stored [j][k] (row len 4096, transposed tile load),
//           kchunk=128, J=512
template <int WHICH>
__global__ __launch_bounds__(256) void gemm_kernel() {
    const float *X, *W;
    float* part;
    int K, J;
    if (WHICH == 0) { X = g_xb1; W = g_M1; part = g_part1; K = NX;  J = LSZ; }
    else            { X = g_xb2; W = g_M2; part = g_part2; K = LSZ; J = FCV; }
    const int kchunk = 128;
    __shared__ float Xs[32][65];
    __shared__ float Ws[32][65];
    int j0 = blockIdx.x * 64;
    int k0 = blockIdx.y * kchunk;
    int tid = threadIdx.x;
    int tb = tid >> 4, tj = tid & 15;
    float acc[4][4] = {};
    for (int kk = k0; kk < k0 + kchunk; kk += 32) {
#pragma unroll
        for (int ld = 0; ld < 8; ld++) {
            int idx = tid + ld * 256;
            int b = idx >> 5;
            int kl = idx & 31;
            Xs[kl][b] = X[b * K + kk + kl];
        }
        if (WHICH == 0) {
#pragma unroll
            for (int ld = 0; ld < 8; ld++) {
                int idx = tid + ld * 256;
                int kl = idx >> 6;
                int jl = idx & 63;
                Ws[kl][jl] = W[(kk + kl) * LSZ + j0 + jl];
            }
        } else {
#pragma unroll
            for (int ld = 0; ld < 8; ld++) {
                int idx = tid + ld * 256;
                int jl = idx >> 5;
                int kl = idx & 31;
                Ws[kl][jl] = W[(j0 + jl) * LSZ + kk + kl];
            }
        }
        __syncthreads();
#pragma unroll
        for (int kl = 0; kl < 32; kl++) {
            float a[4], b[4];
#pragma unroll
            for (int p = 0; p < 4; p++) a[p] = Xs[kl][tb * 4 + p];
#pragma unroll
            for (int q = 0; q < 4; q++) b[q] = Ws[kl][tj * 4 + q];
#pragma unroll
            for (int p = 0; p < 4; p++)
#pragma unroll
                for (int q = 0; q < 4; q++) acc[p][q] += a[p] * b[q];
        }
        __syncthreads();
    }
    int split = blockIdx.y;
#pragma unroll
    for (int p = 0; p < 4; p++)
#pragma unroll
        for (int q = 0; q < 4; q++) {
            int b = tb * 4 + p;
            int j = j0 + tj * 4 + q;
            part[(split * NBATCH + b) * J + j] = acc[p][q];
        }
}

// ---------------- epilogues ----------------
__global__ void epi1_kernel(const float* __restrict__ bias1) {
    int i = blockIdx.x * 256 + threadIdx.x;
    if (i >= NBATCH * LSZ) return;
    int j = i & (LSZ - 1);
    float a = 0.f;
#pragma unroll
    for (int s = 0; s < KSPLIT1; s++) a += g_part1[s * (NBATCH * LSZ) + i];
    float v = a * g_da1[j] + bias1[j];
    v = v > 0.f ? v : 0.f;
    g_xb2[i] = v * g_db2[j];
}

__global__ void epi2_kernel(const float* __restrict__ bias2) {
    int i = blockIdx.x * 256 + threadIdx.x;
    if (i >= NBATCH * FCV) return;
    int j = i & (FCV - 1);
    float a = 0.f;
#pragma unroll
    for (int s = 0; s < KSPLIT2; s++) a += g_part2[s * (NBATCH * FCV) + i];
    float v = a * g_da2[j] + bias2[j];
    g_h2[i] = v > 0.f ? v : 0.f;
}

// ---------------- classifier: out[b][c] = h2[b] . W[c] + bias ----------------
__global__ void logits_kernel(const float* __restrict__ Wl,
                              const float* __restrict__ bl,
                              float* __restrict__ out) {
    int b = blockIdx.x;
    int w = threadIdx.x >> 5;
    int lane = threadIdx.x & 31;
    if (w >= NCLS) return;
    float a = 0.f;
    for (int j = lane; j < FCV; j += 32) a += g_h2[b * FCV + j] * Wl[w * FCV + j];
#pragma unroll
    for (int off = 16; off; off >>= 1) a += __shfl_xor_sync(0xffffffffu, a, off);
    if (lane == 0) out[b * NCLS + w] = a + bl[w];
}

extern "C" void kernel_launch(void* const* d_in, const int* in_sizes, int n_in,
                              void* d_out, int out_size) {
    const float* x    = (const float*)d_in[0];
    const float* G1   = (const float*)d_in[1];
    const float* H1   = (const float*)d_in[2];
    const float* sA1  = (const float*)d_in[3];
    const float* sB1  = (const float*)d_in[4];
    const float* b1   = (const float*)d_in[5];
    const float* G2   = (const float*)d_in[6];
    const float* H2   = (const float*)d_in[7];
    const float* sA2  = (const float*)d_in[8];
    const float* sB2  = (const float*)d_in[9];
    const float* b2   = (const float*)d_in[10];
    const float* Wl   = (const float*)d_in[11];
    const float* bl   = (const float*)d_in[12];
    float* out = (float*)d_out;

    cumprod_kernel<<<4, 256>>>(sA1, sB1, sA2, sB2);
    scale_kernel<<<(R1V * LSZ + 255) / 256, 256>>>(x, G1, H1, G2, H2);

    // Both layers' S = rank-r outer product, then both diagonal scans together.
    sgemm_kernel<<<dim3(LSZ / 64, NX / 64 + FCV / 64), 256>>>();
    segsum_kernel<<<(C1 + C2 + 255) / 256, 256>>>();
    segscan_kernel<<<(C1 + C2 + 255) / 256, 256>>>();

    // Layer 1 apply: y1 = xb1 @ M1t, then bias/ReLU/rescale into xb2.
    gemm_kernel<0><<<dim3(LSZ / 64, KSPLIT1), 256>>>();
    epi1_kernel<<<(NBATCH * LSZ) / 256, 256>>>(b1);

    // Layer 2 apply: y2 = xb2 @ M2^T (512 rows), bias/ReLU.
    gemm_kernel<1><<<dim3(FCV / 64, KSPLIT2), 256>>>();
    epi2_kernel<<<(NBATCH * FCV) / 256, 256>>>(b2);

    logits_kernel<<<NBATCH, 320>>>(Wl, bl, out);
}